// round 1
// baseline (speedup 1.0000x reference)
#include <cuda_runtime.h>
#include <math.h>

// ---------------------------------------------------------------------------
// BilinearAttention: out = softmax(mask( (M@W) @ M^T * adj )) @ M
// B=4, S=4096, H=256, fp32 throughout.
//
// Phase 1: g_inter  = matrix @ W            (16384 x 256 x 256)
// Phase 2: g_scores = g_inter @ matrix^T    (per batch 4096 x 4096 x 256)
//          fused epilogue: *adj, key-mask -> -1e30
// Phase 3: row softmax over g_scores (in place)
// Phase 4: out = g_scores @ matrix          (per batch 4096 x 256 x 4096)
// ---------------------------------------------------------------------------

#define BM 128
#define BN 128
#define BK 16
#define TM 8
#define TN 8
#define NTHREADS 256
#define NEG_INF_F (-1e30f)

#define BATCH 4
#define SEQ   4096
#define HID   256

// Scratch (allocation-free rule: __device__ globals)
__device__ float g_inter[(size_t)BATCH * SEQ * HID];           // 16.8 MB
__device__ float g_scores[(size_t)BATCH * SEQ * SEQ];          // 268 MB

// ---------------------------------------------------------------------------
// Generic SGEMM: C[M,N] = A[M,K] * B
//   BT=false : B is (K x N) row-major
//   BT=true  : B is (N x K) row-major (i.e. C = A * B^T)
//   EPI_ADJ  : epilogue s = acc*adj, masked keys -> -1e30
// 128x128 tile, BK=16, 8x8 per thread, double-buffered smem.
// All dims assumed divisible by tile sizes (true for this problem).
// ---------------------------------------------------------------------------
template<bool BT, bool EPI_ADJ>
__global__ __launch_bounds__(NTHREADS)
void sgemm(const float* __restrict__ Ag, const float* __restrict__ Bg,
           float* __restrict__ Cg,
           const float* __restrict__ adjg, const int* __restrict__ maskg,
           int M, int N, int K,
           size_t sA, size_t sB, size_t sC)
{
    const int b = blockIdx.z;
    const float* A = Ag + (size_t)b * sA;
    const float* B = Bg + (size_t)b * sB;
    float*       C = Cg + (size_t)b * sC;

    const int m0 = blockIdx.y * BM;
    const int n0 = blockIdx.x * BN;

    __shared__ __align__(16) float As[2][BK][BM];
    __shared__ __align__(16) float Bs[2][BK][BN];

    const int tid = threadIdx.x;
    const int tx  = tid & 15;       // 0..15  (col group)
    const int ty  = tid >> 4;       // 0..15  (row group)

    // A / B^T loader mapping: 128 rows x 16 k, each thread 2 float4 (k-contig)
    const int la_m  = tid >> 2;          // 0..63 (+64)
    const int la_k4 = (tid & 3) * 4;     // 0,4,8,12
    // B NN loader mapping: 16 k x 128 n
    const int lb_k  = tid >> 5;          // 0..7 (+8)
    const int lb_n  = (tid & 31) * 4;    // 0..124

    float acc[TM][TN];
    #pragma unroll
    for (int i = 0; i < TM; i++)
        #pragma unroll
        for (int j = 0; j < TN; j++)
            acc[i][j] = 0.0f;

    // ---- prologue: tile 0 straight into smem buffer 0 ----
    {
        #pragma unroll
        for (int i = 0; i < 2; i++) {
            int m = la_m + i * 64;
            float4 v = *(const float4*)(&A[(size_t)(m0 + m) * K + la_k4]);
            As[0][la_k4 + 0][m] = v.x;
            As[0][la_k4 + 1][m] = v.y;
            As[0][la_k4 + 2][m] = v.z;
            As[0][la_k4 + 3][m] = v.w;
        }
        if (BT) {
            #pragma unroll
            for (int i = 0; i < 2; i++) {
                int n = la_m + i * 64;
                float4 v = *(const float4*)(&B[(size_t)(n0 + n) * K + la_k4]);
                Bs[0][la_k4 + 0][n] = v.x;
                Bs[0][la_k4 + 1][n] = v.y;
                Bs[0][la_k4 + 2][n] = v.z;
                Bs[0][la_k4 + 3][n] = v.w;
            }
        } else {
            #pragma unroll
            for (int i = 0; i < 2; i++) {
                int k = lb_k + i * 8;
                *(float4*)(&Bs[0][k][lb_n]) =
                    *(const float4*)(&B[(size_t)k * N + n0 + lb_n]);
            }
        }
    }
    __syncthreads();

    const int ntiles = K / BK;
    for (int t = 0; t < ntiles; t++) {
        const int cur = t & 1;
        float4 stA0, stA1, stB0, stB1;
        const bool has_next = (t + 1 < ntiles);
        if (has_next) {
            const int k0 = (t + 1) * BK;
            stA0 = *(const float4*)(&A[(size_t)(m0 + la_m) * K + k0 + la_k4]);
            stA1 = *(const float4*)(&A[(size_t)(m0 + la_m + 64) * K + k0 + la_k4]);
            if (BT) {
                stB0 = *(const float4*)(&B[(size_t)(n0 + la_m) * K + k0 + la_k4]);
                stB1 = *(const float4*)(&B[(size_t)(n0 + la_m + 64) * K + k0 + la_k4]);
            } else {
                stB0 = *(const float4*)(&B[(size_t)(k0 + lb_k) * N + n0 + lb_n]);
                stB1 = *(const float4*)(&B[(size_t)(k0 + lb_k + 8) * N + n0 + lb_n]);
            }
        }

        // compute on current buffer
        #pragma unroll
        for (int k = 0; k < BK; k++) {
            float a[TM], bb[TN];
            #pragma unroll
            for (int i = 0; i < TM; i += 4)
                *(float4*)&a[i] = *(const float4*)&As[cur][k][ty * TM + i];
            #pragma unroll
            for (int j = 0; j < TN; j += 4)
                *(float4*)&bb[j] = *(const float4*)&Bs[cur][k][tx * TN + j];
            #pragma unroll
            for (int i = 0; i < TM; i++)
                #pragma unroll
                for (int j = 0; j < TN; j++)
                    acc[i][j] = fmaf(a[i], bb[j], acc[i][j]);
        }

        if (has_next) {
            const int nxt = cur ^ 1;
            As[nxt][la_k4 + 0][la_m]      = stA0.x;
            As[nxt][la_k4 + 1][la_m]      = stA0.y;
            As[nxt][la_k4 + 2][la_m]      = stA0.z;
            As[nxt][la_k4 + 3][la_m]      = stA0.w;
            As[nxt][la_k4 + 0][la_m + 64] = stA1.x;
            As[nxt][la_k4 + 1][la_m + 64] = stA1.y;
            As[nxt][la_k4 + 2][la_m + 64] = stA1.z;
            As[nxt][la_k4 + 3][la_m + 64] = stA1.w;
            if (BT) {
                Bs[nxt][la_k4 + 0][la_m]      = stB0.x;
                Bs[nxt][la_k4 + 1][la_m]      = stB0.y;
                Bs[nxt][la_k4 + 2][la_m]      = stB0.z;
                Bs[nxt][la_k4 + 3][la_m]      = stB0.w;
                Bs[nxt][la_k4 + 0][la_m + 64] = stB1.x;
                Bs[nxt][la_k4 + 1][la_m + 64] = stB1.y;
                Bs[nxt][la_k4 + 2][la_m + 64] = stB1.z;
                Bs[nxt][la_k4 + 3][la_m + 64] = stB1.w;
            } else {
                *(float4*)(&Bs[nxt][lb_k][lb_n])     = stB0;
                *(float4*)(&Bs[nxt][lb_k + 8][lb_n]) = stB1;
            }
        }
        __syncthreads();
    }

    // ---- epilogue ----
    if (EPI_ADJ) {
        const float* adj = adjg + (size_t)b * sC;   // same shape as C
        const int*   mk  = maskg + b * SEQ;         // N == SEQ here
        int msk[TN];
        #pragma unroll
        for (int j = 0; j < TN; j++)
            msk[j] = mk[n0 + tx * TN + j];
        #pragma unroll
        for (int i = 0; i < TM; i++) {
            const size_t ro = (size_t)(m0 + ty * TM + i) * N;
            #pragma unroll
            for (int j = 0; j < TN; j += 4) {
                const int gj = n0 + tx * TN + j;
                float4 av = *(const float4*)(&adj[ro + gj]);
                float4 r;
                r.x = msk[j + 0] ? acc[i][j + 0] * av.x : NEG_INF_F;
                r.y = msk[j + 1] ? acc[i][j + 1] * av.y : NEG_INF_F;
                r.z = msk[j + 2] ? acc[i][j + 2] * av.z : NEG_INF_F;
                r.w = msk[j + 3] ? acc[i][j + 3] * av.w : NEG_INF_F;
                *(float4*)(&C[ro + gj]) = r;
            }
        }
    } else {
        #pragma unroll
        for (int i = 0; i < TM; i++) {
            const size_t ro = (size_t)(m0 + ty * TM + i) * N;
            #pragma unroll
            for (int j = 0; j < TN; j += 4)
                *(float4*)(&C[ro + n0 + tx * TN + j]) = *(float4*)&acc[i][j];
        }
    }
}

// ---------------------------------------------------------------------------
// Row softmax over 4096-wide rows, in place. One block per row.
// Matches JAX semantics incl. the all-masked row case (uniform output).
// ---------------------------------------------------------------------------
__global__ __launch_bounds__(256)
void softmax_rows(float* __restrict__ S)
{
    const size_t row = blockIdx.x;
    float* p = S + row * (size_t)SEQ;
    const int tid = threadIdx.x;

    float4 v[4];
    #pragma unroll
    for (int i = 0; i < 4; i++)
        v[i] = *(const float4*)(&p[(size_t)(i * 256 + tid) * 4]);

    __shared__ float red[8];

    // max
    float mx = v[0].x;
    #pragma unroll
    for (int i = 0; i < 4; i++)
        mx = fmaxf(mx, fmaxf(fmaxf(v[i].x, v[i].y), fmaxf(v[i].z, v[i].w)));
    #pragma unroll
    for (int o = 16; o > 0; o >>= 1)
        mx = fmaxf(mx, __shfl_xor_sync(0xffffffffu, mx, o));
    if ((tid & 31) == 0) red[tid >> 5] = mx;
    __syncthreads();
    if (tid < 32) {
        float m2 = (tid < 8) ? red[tid] : -INFINITY;
        #pragma unroll
        for (int o = 4; o > 0; o >>= 1)
            m2 = fmaxf(m2, __shfl_xor_sync(0xffffffffu, m2, o));
        if (tid == 0) red[0] = m2;
    }
    __syncthreads();
    mx = red[0];
    __syncthreads();   // protect red[] before reuse

    // exp + sum
    float s = 0.0f;
    #pragma unroll
    for (int i = 0; i < 4; i++) {
        v[i].x = expf(v[i].x - mx); s += v[i].x;
        v[i].y = expf(v[i].y - mx); s += v[i].y;
        v[i].z = expf(v[i].z - mx); s += v[i].z;
        v[i].w = expf(v[i].w - mx); s += v[i].w;
    }
    #pragma unroll
    for (int o = 16; o > 0; o >>= 1)
        s += __shfl_xor_sync(0xffffffffu, s, o);
    if ((tid & 31) == 0) red[tid >> 5] = s;
    __syncthreads();
    if (tid < 32) {
        float s2 = (tid < 8) ? red[tid] : 0.0f;
        #pragma unroll
        for (int o = 4; o > 0; o >>= 1)
            s2 += __shfl_xor_sync(0xffffffffu, s2, o);
        if (tid == 0) red[0] = s2;
    }
    __syncthreads();
    const float inv = 1.0f / red[0];

    #pragma unroll
    for (int i = 0; i < 4; i++) {
        v[i].x *= inv; v[i].y *= inv; v[i].z *= inv; v[i].w *= inv;
        *(float4*)(&p[(size_t)(i * 256 + tid) * 4]) = v[i];
    }
}

// ---------------------------------------------------------------------------
// Launch
// ---------------------------------------------------------------------------
extern "C" void kernel_launch(void* const* d_in, const int* in_sizes, int n_in,
                              void* d_out, int out_size)
{
    (void)in_sizes; (void)n_in; (void)out_size;
    const float* matrix = (const float*)d_in[0];   // (4, 4096, 256) f32
    const int*   mask   = (const int*)d_in[1];     // (4, 4096) i32
    const float* adj    = (const float*)d_in[2];   // (4, 4096, 4096) f32
    const float* W      = (const float*)d_in[3];   // (256, 256) f32
    float* out = (float*)d_out;                    // (4, 4096, 256) f32

    static float* p_inter  = nullptr;
    static float* p_scores = nullptr;
    if (p_inter == nullptr) {
        cudaGetSymbolAddress((void**)&p_inter,  g_inter);
        cudaGetSymbolAddress((void**)&p_scores, g_scores);
    }

    const dim3 blk(NTHREADS);

    // Phase 1: I = matrix @ W       (M=16384, N=256, K=256)
    sgemm<false, false><<<dim3(HID / BN, (BATCH * SEQ) / BM, 1), blk>>>(
        matrix, W, p_inter, nullptr, nullptr,
        BATCH * SEQ, HID, HID, 0, 0, 0);

    // Phase 2: S = I @ M^T * adj, masked   (per batch: M=N=4096, K=256)
    sgemm<true, true><<<dim3(SEQ / BN, SEQ / BM, BATCH), blk>>>(
        p_inter, matrix, p_scores, adj, mask,
        SEQ, SEQ, HID,
        (size_t)SEQ * HID, (size_t)SEQ * HID, (size_t)SEQ * SEQ);

    // Phase 3: row softmax in place
    softmax_rows<<<BATCH * SEQ, 256>>>(p_scores);

    // Phase 4: out = P @ M          (per batch: M=4096, N=256, K=4096)
    sgemm<false, false><<<dim3(HID / BN, SEQ / BM, BATCH), blk>>>(
        p_scores, matrix, out, nullptr, nullptr,
        SEQ, HID, SEQ,
        (size_t)SEQ * SEQ, (size_t)SEQ * HID, (size_t)SEQ * HID);
}

// round 4
// speedup vs baseline: 2.3155x; 2.3155x over previous
#include <cuda_runtime.h>
#include <cuda_bf16.h>
#include <math.h>
#include <stdint.h>

typedef __nv_bfloat16 bf16;

#define BATCH 4
#define SEQ   4096
#define HID   256
#define NEG_INF_F (-1e30f)

// ---------------------------------------------------------------------------
// Scratch (__device__ globals: allocation-free rule)
// ---------------------------------------------------------------------------
__device__ float g_inter [(size_t)BATCH * SEQ * HID];   // 16.8 MB fp32
__device__ float g_scores[(size_t)BATCH * SEQ * SEQ];   // 268 MB fp32
__device__ bf16  g_ihi [(size_t)BATCH * SEQ * HID];     // inter hi
__device__ bf16  g_ilo [(size_t)BATCH * SEQ * HID];     // inter lo
__device__ bf16  g_mhi [(size_t)BATCH * SEQ * HID];     // matrix hi
__device__ bf16  g_mlo [(size_t)BATCH * SEQ * HID];     // matrix lo
__device__ bf16  g_mthi[(size_t)BATCH * HID * SEQ];     // matrix^T hi
__device__ bf16  g_mtlo[(size_t)BATCH * HID * SEQ];     // matrix^T lo
__device__ bf16  g_phi [(size_t)BATCH * SEQ * SEQ];     // attn P hi (134 MB)
__device__ bf16  g_plo [(size_t)BATCH * SEQ * SEQ];     // attn P lo (134 MB)

// ---------------------------------------------------------------------------
// Helpers
// ---------------------------------------------------------------------------
__device__ __forceinline__ uint32_t smem_u32(const void* p) {
    uint32_t a;
    asm("{ .reg .u64 t; cvta.to.shared.u64 t, %1; cvt.u32.u64 %0, t; }"
        : "=r"(a) : "l"(p));
    return a;
}

#define CP_ASYNC16(dst, src) \
    asm volatile("cp.async.cg.shared.global [%0], [%1], 16;" \
                 :: "r"(dst), "l"(src) : "memory")
#define CP_COMMIT() asm volatile("cp.async.commit_group;" ::: "memory")
#define CP_WAIT1()  asm volatile("cp.async.wait_group 1;" ::: "memory")
#define CP_WAIT0()  asm volatile("cp.async.wait_group 0;" ::: "memory")

// D += A*B  (m16n8k16, bf16 in, fp32 accumulate)
__device__ __forceinline__ void mma16816(float* d, const uint32_t* a,
                                         const uint32_t* b) {
    asm volatile(
        "mma.sync.aligned.m16n8k16.row.col.f32.bf16.bf16.f32 "
        "{%0,%1,%2,%3}, {%4,%5,%6,%7}, {%8,%9}, {%0,%1,%2,%3};\n"
        : "+f"(d[0]), "+f"(d[1]), "+f"(d[2]), "+f"(d[3])
        : "r"(a[0]), "r"(a[1]), "r"(a[2]), "r"(a[3]), "r"(b[0]), "r"(b[1]));
}

// ---------------------------------------------------------------------------
// Tensor GEMM (legacy HMMA): C[m,n] = sum_k (Ahi+Alo)[m,k]*(Bhi+Blo)[n,k]
// 3-term bf16 split (hh + hl + lh), fp32 accumulators.
// Block 128x128, KC=32 chunks, cp.async double buffer, 8 warps (4m x 2n),
// warp tile 32x64 = 2x8 m16n8k16 atoms.
// EPI_ADJ: C = mask ? acc*adj : -1e30
// ---------------------------------------------------------------------------
#define BMG 128
#define BNG 128
#define KCG 32
#define KCP 40                      // padded pitch (elements)
#define ARR_B (128 * KCP * 2)       // 10240 B per array
#define STG_B (4 * ARR_B)           // Ahi, Alo, Bhi, Blo = 40960 B
#define SMEM_G (2 * STG_B)          // 81920 B

template<bool EPI_ADJ>
__global__ __launch_bounds__(256)
void mma_gemm(const bf16* __restrict__ Ahi_g, const bf16* __restrict__ Alo_g,
              const bf16* __restrict__ Bhi_g, const bf16* __restrict__ Blo_g,
              float* __restrict__ Cg, const float* __restrict__ adjg,
              const int* __restrict__ maskg,
              int K, int Ntot, size_t sA, size_t sB, size_t sC)
{
    extern __shared__ char smem[];
    const uint32_t sb = smem_u32(smem);
    const int tid = threadIdx.x, lane = tid & 31, wid = tid >> 5;
    const int b  = blockIdx.z;
    const int m0 = blockIdx.y * BMG;
    const int n0 = blockIdx.x * BNG;
    const int wm = (wid & 3) * 32;   // warp m offset
    const int wn = (wid >> 2) * 64;  // warp n offset

    const bf16* __restrict__ Ahi = Ahi_g + (size_t)b * sA;
    const bf16* __restrict__ Alo = Alo_g + (size_t)b * sA;
    const bf16* __restrict__ Bhi = Bhi_g + (size_t)b * sB;
    const bf16* __restrict__ Blo = Blo_g + (size_t)b * sB;

    // loader: 4 arrays x 128 rows x 64B (= 32 bf16) per chunk, 16B cp.async
    auto load_chunk = [&](int c, int s) {
        const uint32_t stb = sb + s * STG_B;
        #pragma unroll
        for (int j = 0; j < 8; j++) {
            const int arr = j >> 1;                    // compile-time
            const int rem = tid + (j & 1) * 256;       // 0..511
            const int row = rem >> 2;
            const int q   = rem & 3;
            const uint32_t dst = stb + arr * ARR_B + row * (KCP * 2) + q * 16;
            const bf16* base = (arr == 0) ? Ahi : (arr == 1) ? Alo
                             : (arr == 2) ? Bhi : Blo;
            const int grow = ((arr < 2) ? m0 : n0) + row;
            const bf16* src = base + (size_t)grow * K + c * KCG + q * 8;
            CP_ASYNC16(dst, src);
        }
    };

    float acc[2][8][4];
    #pragma unroll
    for (int ma = 0; ma < 2; ma++)
        #pragma unroll
        for (int na = 0; na < 8; na++)
            #pragma unroll
            for (int r = 0; r < 4; r++) acc[ma][na][r] = 0.0f;

    load_chunk(0, 0);
    CP_COMMIT();

    const int NC = K / KCG;
    const int lk = (lane & 3) * 2;       // k element offset within 16
    const int lr = lane >> 2;            // row within 8

    for (int c = 0; c < NC; c++) {
        if (c + 1 < NC) { load_chunk(c + 1, (c + 1) & 1); CP_COMMIT(); CP_WAIT1(); }
        else           { CP_WAIT0(); }
        __syncthreads();

        const char* st = smem + (c & 1) * STG_B;
        #pragma unroll
        for (int ks = 0; ks < 2; ks++) {
            const int ke = ks * 16 + lk;   // element offset in chunk
            // B fragments (hi & lo) for the 8 n-atoms
            uint32_t bh[8][2], bl[8][2];
            #pragma unroll
            for (int na = 0; na < 8; na++) {
                const char* pb = st + 2 * ARR_B
                               + (wn + na * 8 + lr) * (KCP * 2) + ke * 2;
                bh[na][0] = *(const uint32_t*)(pb);
                bh[na][1] = *(const uint32_t*)(pb + 16);
                bl[na][0] = *(const uint32_t*)(pb + ARR_B);
                bl[na][1] = *(const uint32_t*)(pb + ARR_B + 16);
            }
            #pragma unroll
            for (int ma = 0; ma < 2; ma++) {
                const char* pa = st + (wm + ma * 16 + lr) * (KCP * 2) + ke * 2;
                uint32_t ah[4], al[4];
                ah[0] = *(const uint32_t*)(pa);
                ah[1] = *(const uint32_t*)(pa + 8 * (KCP * 2));
                ah[2] = *(const uint32_t*)(pa + 16);
                ah[3] = *(const uint32_t*)(pa + 8 * (KCP * 2) + 16);
                al[0] = *(const uint32_t*)(pa + ARR_B);
                al[1] = *(const uint32_t*)(pa + ARR_B + 8 * (KCP * 2));
                al[2] = *(const uint32_t*)(pa + ARR_B + 16);
                al[3] = *(const uint32_t*)(pa + ARR_B + 8 * (KCP * 2) + 16);
                #pragma unroll
                for (int na = 0; na < 8; na++) {
                    mma16816(acc[ma][na], ah, bh[na]);
                    mma16816(acc[ma][na], ah, bl[na]);
                    mma16816(acc[ma][na], al, bh[na]);
                }
            }
        }
        __syncthreads();
    }

    // stage key mask (n-tile) into smem (pipeline done; safe to reuse)
    if (EPI_ADJ) {
        if (tid < 128) ((int*)smem)[tid] = maskg[b * SEQ + n0 + tid];
        __syncthreads();
    }

    // epilogue
    const int* mk = (const int*)smem;
    #pragma unroll
    for (int ma = 0; ma < 2; ma++) {
        #pragma unroll
        for (int half = 0; half < 2; half++) {
            const int r = m0 + wm + ma * 16 + lr + half * 8;
            float* Crow = Cg + (size_t)b * sC + (size_t)r * Ntot + n0;
            const float* arow = EPI_ADJ
                ? adjg + (size_t)b * sC + (size_t)r * Ntot + n0
                : (const float*)0;
            #pragma unroll
            for (int na = 0; na < 8; na++) {
                const int cc = wn + na * 8 + lk;
                float2 v;
                v.x = acc[ma][na][half * 2 + 0];
                v.y = acc[ma][na][half * 2 + 1];
                if (EPI_ADJ) {
                    float2 av = *(const float2*)(arow + cc);
                    v.x = mk[cc + 0] ? v.x * av.x : NEG_INF_F;
                    v.y = mk[cc + 1] ? v.y * av.y : NEG_INF_F;
                }
                *(float2*)(Crow + cc) = v;
            }
        }
    }
}

// ---------------------------------------------------------------------------
// Phase 1: inter = matrix @ W  (fp32 SGEMM, 128x128x16, double-buffered)
// ---------------------------------------------------------------------------
#define BM 128
#define BN 128
#define BK 16
#define TM 8
#define TN 8

__global__ __launch_bounds__(256)
void sgemm_nn(const float* __restrict__ A, const float* __restrict__ B,
              float* __restrict__ C, int M, int N, int K)
{
    const int m0 = blockIdx.y * BM;
    const int n0 = blockIdx.x * BN;

    __shared__ __align__(16) float As[2][BK][BM];
    __shared__ __align__(16) float Bs[2][BK][BN];

    const int tid = threadIdx.x;
    const int tx = tid & 15, ty = tid >> 4;
    const int la_m = tid >> 2, la_k4 = (tid & 3) * 4;
    const int lb_k = tid >> 5, lb_n = (tid & 31) * 4;

    float acc[TM][TN];
    #pragma unroll
    for (int i = 0; i < TM; i++)
        #pragma unroll
        for (int j = 0; j < TN; j++) acc[i][j] = 0.0f;

    #pragma unroll
    for (int i = 0; i < 2; i++) {
        int m = la_m + i * 64;
        float4 v = *(const float4*)(&A[(size_t)(m0 + m) * K + la_k4]);
        As[0][la_k4 + 0][m] = v.x; As[0][la_k4 + 1][m] = v.y;
        As[0][la_k4 + 2][m] = v.z; As[0][la_k4 + 3][m] = v.w;
    }
    #pragma unroll
    for (int i = 0; i < 2; i++) {
        int k = lb_k + i * 8;
        *(float4*)(&Bs[0][k][lb_n]) = *(const float4*)(&B[(size_t)k * N + n0 + lb_n]);
    }
    __syncthreads();

    const int ntiles = K / BK;
    for (int t = 0; t < ntiles; t++) {
        const int cur = t & 1;
        float4 stA0, stA1, stB0, stB1;
        const bool has_next = (t + 1 < ntiles);
        if (has_next) {
            const int k0 = (t + 1) * BK;
            stA0 = *(const float4*)(&A[(size_t)(m0 + la_m) * K + k0 + la_k4]);
            stA1 = *(const float4*)(&A[(size_t)(m0 + la_m + 64) * K + k0 + la_k4]);
            stB0 = *(const float4*)(&B[(size_t)(k0 + lb_k) * N + n0 + lb_n]);
            stB1 = *(const float4*)(&B[(size_t)(k0 + lb_k + 8) * N + n0 + lb_n]);
        }
        #pragma unroll
        for (int k = 0; k < BK; k++) {
            float a[TM], bb[TN];
            #pragma unroll
            for (int i = 0; i < TM; i += 4)
                *(float4*)&a[i] = *(const float4*)&As[cur][k][ty * TM + i];
            #pragma unroll
            for (int j = 0; j < TN; j += 4)
                *(float4*)&bb[j] = *(const float4*)&Bs[cur][k][tx * TN + j];
            #pragma unroll
            for (int i = 0; i < TM; i++)
                #pragma unroll
                for (int j = 0; j < TN; j++)
                    acc[i][j] = fmaf(a[i], bb[j], acc[i][j]);
        }
        if (has_next) {
            const int nxt = cur ^ 1;
            As[nxt][la_k4 + 0][la_m]      = stA0.x; As[nxt][la_k4 + 1][la_m]      = stA0.y;
            As[nxt][la_k4 + 2][la_m]      = stA0.z; As[nxt][la_k4 + 3][la_m]      = stA0.w;
            As[nxt][la_k4 + 0][la_m + 64] = stA1.x; As[nxt][la_k4 + 1][la_m + 64] = stA1.y;
            As[nxt][la_k4 + 2][la_m + 64] = stA1.z; As[nxt][la_k4 + 3][la_m + 64] = stA1.w;
            *(float4*)(&Bs[nxt][lb_k][lb_n])     = stB0;
            *(float4*)(&Bs[nxt][lb_k + 8][lb_n]) = stB1;
        }
        __syncthreads();
    }

    #pragma unroll
    for (int i = 0; i < TM; i++) {
        const size_t ro = (size_t)(m0 + ty * TM + i) * N;
        #pragma unroll
        for (int j = 0; j < TN; j += 4)
            *(float4*)(&C[ro + n0 + tx * TN + j]) = *(float4*)&acc[i][j];
    }
}

// ---------------------------------------------------------------------------
// bf16 hi/lo split helpers
// ---------------------------------------------------------------------------
__device__ __forceinline__ void split2(float v, bf16& h, bf16& l) {
    h = __float2bfloat16(v);
    l = __float2bfloat16(v - __bfloat162float(h));
}

__global__ __launch_bounds__(256)
void split_f32(const float* __restrict__ x, bf16* __restrict__ hi,
               bf16* __restrict__ lo, size_t n)
{
    size_t i = (size_t)blockIdx.x * blockDim.x + threadIdx.x;
    if (i < n) { bf16 h, l; split2(x[i], h, l); hi[i] = h; lo[i] = l; }
}

// matrix -> mhi/mlo (same layout) + mthi/mtlo (transposed [b][h][t])
__global__ __launch_bounds__(256)
void split_transpose(const float* __restrict__ m, bf16* __restrict__ mhi,
                     bf16* __restrict__ mlo, bf16* __restrict__ mthi,
                     bf16* __restrict__ mtlo)
{
    __shared__ float tile[32][33];
    const int b = blockIdx.z;
    const int h0 = blockIdx.x * 32, t0 = blockIdx.y * 32;
    const int tx = threadIdx.x, ty = threadIdx.y;   // 32 x 8
    const size_t mb = (size_t)b * SEQ * HID;
    #pragma unroll
    for (int r = 0; r < 32; r += 8) {
        float v = m[mb + (size_t)(t0 + ty + r) * HID + h0 + tx];
        tile[ty + r][tx] = v;
        bf16 h, l; split2(v, h, l);
        mhi[mb + (size_t)(t0 + ty + r) * HID + h0 + tx] = h;
        mlo[mb + (size_t)(t0 + ty + r) * HID + h0 + tx] = l;
    }
    __syncthreads();
    const size_t tb = (size_t)b * HID * SEQ;
    #pragma unroll
    for (int r = 0; r < 32; r += 8) {
        float v = tile[tx][ty + r];   // = m[t0+tx][h0+ty+r]
        bf16 h, l; split2(v, h, l);
        mthi[tb + (size_t)(h0 + ty + r) * SEQ + t0 + tx] = h;
        mtlo[tb + (size_t)(h0 + ty + r) * SEQ + t0 + tx] = l;
    }
}

// ---------------------------------------------------------------------------
// Row softmax (4096 wide) reading fp32 scores, writing P as bf16 hi/lo
// ---------------------------------------------------------------------------
__global__ __launch_bounds__(256)
void softmax_split(const float* __restrict__ S, bf16* __restrict__ Phi,
                   bf16* __restrict__ Plo)
{
    const size_t row = blockIdx.x;
    const float* p = S + row * (size_t)SEQ;
    const int tid = threadIdx.x;

    float4 v[4];
    #pragma unroll
    for (int i = 0; i < 4; i++)
        v[i] = *(const float4*)(&p[(size_t)(i * 256 + tid) * 4]);

    __shared__ float red[8];

    float mx = v[0].x;
    #pragma unroll
    for (int i = 0; i < 4; i++)
        mx = fmaxf(mx, fmaxf(fmaxf(v[i].x, v[i].y), fmaxf(v[i].z, v[i].w)));
    #pragma unroll
    for (int o = 16; o > 0; o >>= 1)
        mx = fmaxf(mx, __shfl_xor_sync(0xffffffffu, mx, o));
    if ((tid & 31) == 0) red[tid >> 5] = mx;
    __syncthreads();
    if (tid < 32) {
        float m2 = (tid < 8) ? red[tid] : -INFINITY;
        #pragma unroll
        for (int o = 4; o > 0; o >>= 1)
            m2 = fmaxf(m2, __shfl_xor_sync(0xffffffffu, m2, o));
        if (tid == 0) red[0] = m2;
    }
    __syncthreads();
    mx = red[0];
    __syncthreads();

    float s = 0.0f;
    #pragma unroll
    for (int i = 0; i < 4; i++) {
        v[i].x = expf(v[i].x - mx); s += v[i].x;
        v[i].y = expf(v[i].y - mx); s += v[i].y;
        v[i].z = expf(v[i].z - mx); s += v[i].z;
        v[i].w = expf(v[i].w - mx); s += v[i].w;
    }
    #pragma unroll
    for (int o = 16; o > 0; o >>= 1)
        s += __shfl_xor_sync(0xffffffffu, s, o);
    if ((tid & 31) == 0) red[tid >> 5] = s;
    __syncthreads();
    if (tid < 32) {
        float s2 = (tid < 8) ? red[tid] : 0.0f;
        #pragma unroll
        for (int o = 4; o > 0; o >>= 1)
            s2 += __shfl_xor_sync(0xffffffffu, s2, o);
        if (tid == 0) red[0] = s2;
    }
    __syncthreads();
    const float inv = 1.0f / red[0];

    #pragma unroll
    for (int i = 0; i < 4; i++) {
        const size_t off = row * (size_t)SEQ + (size_t)(i * 256 + tid) * 4;
        float pv[4] = { v[i].x * inv, v[i].y * inv, v[i].z * inv, v[i].w * inv };
        ushort4 uh, ul;
        bf16 h, l;
        split2(pv[0], h, l); uh.x = __bfloat16_as_ushort(h); ul.x = __bfloat16_as_ushort(l);
        split2(pv[1], h, l); uh.y = __bfloat16_as_ushort(h); ul.y = __bfloat16_as_ushort(l);
        split2(pv[2], h, l); uh.z = __bfloat16_as_ushort(h); ul.z = __bfloat16_as_ushort(l);
        split2(pv[3], h, l); uh.w = __bfloat16_as_ushort(h); ul.w = __bfloat16_as_ushort(l);
        *(ushort4*)(Phi + off) = uh;
        *(ushort4*)(Plo + off) = ul;
    }
}

// ---------------------------------------------------------------------------
// Launch
// ---------------------------------------------------------------------------
extern "C" void kernel_launch(void* const* d_in, const int* in_sizes, int n_in,
                              void* d_out, int out_size)
{
    (void)in_sizes; (void)n_in; (void)out_size;
    const float* matrix = (const float*)d_in[0];   // (4, 4096, 256) f32
    const int*   mask   = (const int*)d_in[1];     // (4, 4096) i32
    const float* adj    = (const float*)d_in[2];   // (4, 4096, 4096) f32
    const float* W      = (const float*)d_in[3];   // (256, 256) f32
    float* out = (float*)d_out;                    // (4, 4096, 256) f32

    static float *p_inter = nullptr, *p_scores = nullptr;
    static bf16 *p_ihi, *p_ilo, *p_mhi, *p_mlo, *p_mthi, *p_mtlo, *p_phi, *p_plo;
    if (p_inter == nullptr) {
        cudaGetSymbolAddress((void**)&p_inter,  g_inter);
        cudaGetSymbolAddress((void**)&p_scores, g_scores);
        cudaGetSymbolAddress((void**)&p_ihi,  g_ihi);
        cudaGetSymbolAddress((void**)&p_ilo,  g_ilo);
        cudaGetSymbolAddress((void**)&p_mhi,  g_mhi);
        cudaGetSymbolAddress((void**)&p_mlo,  g_mlo);
        cudaGetSymbolAddress((void**)&p_mthi, g_mthi);
        cudaGetSymbolAddress((void**)&p_mtlo, g_mtlo);
        cudaGetSymbolAddress((void**)&p_phi,  g_phi);
        cudaGetSymbolAddress((void**)&p_plo,  g_plo);
        cudaFuncSetAttribute(mma_gemm<true>,
            cudaFuncAttributeMaxDynamicSharedMemorySize, SMEM_G);
        cudaFuncSetAttribute(mma_gemm<false>,
            cudaFuncAttributeMaxDynamicSharedMemorySize, SMEM_G);
    }

    // Phase 1: inter = matrix @ W (fp32)
    sgemm_nn<<<dim3(HID / BN, (BATCH * SEQ) / BM), 256>>>(
        matrix, W, p_inter, BATCH * SEQ, HID, HID);

    // Prep: split inter; split + transpose matrix
    {
        const size_t n = (size_t)BATCH * SEQ * HID;
        split_f32<<<(unsigned)((n + 255) / 256), 256>>>(p_inter, p_ihi, p_ilo, n);
        split_transpose<<<dim3(HID / 32, SEQ / 32, BATCH), dim3(32, 8)>>>(
            matrix, p_mhi, p_mlo, p_mthi, p_mtlo);
    }

    // Phase 2: scores = (inter @ matrix^T) * adj, masked  (HMMA, bf16x3)
    mma_gemm<true><<<dim3(SEQ / BNG, SEQ / BMG, BATCH), 256, SMEM_G>>>(
        p_ihi, p_ilo, p_mhi, p_mlo, p_scores, adj, mask,
        HID, SEQ, (size_t)SEQ * HID, (size_t)SEQ * HID, (size_t)SEQ * SEQ);

    // Phase 3: softmax rows -> P hi/lo bf16
    softmax_split<<<BATCH * SEQ, 256>>>(p_scores, p_phi, p_plo);

    // Phase 4: out = P @ matrix  (HMMA, bf16x3; B = matrix^T hi/lo, K=4096)
    mma_gemm<false><<<dim3(HID / BNG, SEQ / BMG, BATCH), 256, SMEM_G>>>(
        p_phi, p_plo, p_mthi, p_mtlo, out, nullptr, nullptr,
        SEQ, HID, (size_t)SEQ * SEQ, (size_t)HID * SEQ, (size_t)SEQ * HID);
}